// round 10
// baseline (speedup 1.0000x reference)
#include <cuda_runtime.h>
#include <cuda_fp16.h>

// Problem dims (fixed by reference)
#define UDIM 400
#define VDIM 400
#define MDIM 4
#define VPAD (VDIM + 1)                    // duplicate column 0 at j=400 -> no j-wrap
#define NTEXP (MDIM * UDIM * VPAD)         // 641,600 padded texels

// Compact fp16 table: per texel one 32B record (16 halves):
// [W00..W22 row-major (9), B0,B1,B2 (3), pad (4)].
// j-contiguous with VPAD -> a (j, j+1) pair is 64B contiguous, 32B-aligned.
// Total 20.5 MB -> L2-resident.
__device__ __align__(32) unsigned g_tbl[(size_t)NTEXP * 8];

__global__ __launch_bounds__(256) void pack_kernel(
    const float* __restrict__ m_param,
    const float* __restrict__ b_param)
{
    int t = blockIdx.x * blockDim.x + threadIdx.x;
    if (t >= NTEXP) return;
    int m  = t / (UDIM * VPAD);
    int r  = t % (UDIM * VPAD);
    int i  = r / VPAD;
    int jp = r % VPAD;
    int j  = (jp == VDIM) ? 0 : jp;         // padded column duplicates j=0
    size_t src = (size_t)(m * UDIM + i) * VDIM + j;

    const float* w = m_param + src * 9;
    const float* b = b_param + src * 3;

    __align__(32) __half h[16];
    #pragma unroll
    for (int k = 0; k < 9; k++) h[k] = __float2half_rn(w[k]);
    #pragma unroll
    for (int k = 0; k < 3; k++) h[9 + k] = __float2half_rn(b[k]);
    h[12] = h[13] = h[14] = h[15] = __half(0.0f);

    const uint4* s = reinterpret_cast<const uint4*>(h);
    uint4* dst = reinterpret_cast<uint4*>(g_tbl + (size_t)t * 8);
    dst[0] = s[0];
    dst[1] = s[1];
}

__device__ __forceinline__ void ldg256(const void* p, unsigned r[8]) {
    asm("ld.global.nc.v8.b32 {%0,%1,%2,%3,%4,%5,%6,%7}, [%8];"
        : "=r"(r[0]), "=r"(r[1]), "=r"(r[2]), "=r"(r[3]),
          "=r"(r[4]), "=r"(r[5]), "=r"(r[6]), "=r"(r[7])
        : "l"(p));
}

// Compute rowA/rowB byte offsets (u32) + 4 bilinear weights for one point.
__device__ __forceinline__ void point_setup(float uu, float vv, int mm,
                                            unsigned& offA, unsigned& offB,
                                            float wgt[4]) {
    float iu = uu * (float)UDIM;
    float iv = vv * (float)VDIM;
    if (iu == (float)UDIM) iu = (float)(UDIM - 1);
    if (iv == (float)VDIM) iv = (float)(VDIM - 1);

    float i1f = floorf(iu);
    float j1f = floorf(iv);
    int i1 = (int)i1f;
    int j1 = (int)j1f;                       // j2 via padded column
    int i2 = i1 + 1; if (i2 == UDIM) i2 = 0; // i wraps
    float ir = iu - i1f;
    float jr = iv - j1f;

    offA = (unsigned)((mm * UDIM + i1) * VPAD + j1) * 32u;
    offB = (unsigned)((mm * UDIM + i2) * VPAD + j1) * 32u;

    wgt[0] = (1.0f - ir) * (1.0f - jr);   // (i1, j1)
    wgt[1] = (1.0f - ir) * jr;            // (i1, j1+1)
    wgt[2] = ir * (1.0f - jr);            // (i2, j1)
    wgt[3] = ir * jr;                     // (i2, j1+1)
}

// Load 4 corner records, blend, matvec -> 3 outputs. Table regs live only here.
__device__ __noinline__ void point_process(const char* base,
                                           unsigned offA, unsigned offB,
                                           const float wgt[4],
                                           float x0, float x1, float x2,
                                           float& o0, float& o1, float& o2) {
    unsigned a1[8], a2[8], b1[8], b2[8];
    ldg256(base + offA,       a1);
    ldg256(base + offA + 32u, a2);
    ldg256(base + offB,       b1);
    ldg256(base + offB + 32u, b2);

    // record half2 slots s=0..5:
    // [0]=(W00,W01) [1]=(W02,W10) [2]=(W11,W12) [3]=(W20,W21) [4]=(W22,B0) [5]=(B1,B2)
    float2 acc[6];
    #pragma unroll
    for (int s = 0; s < 6; s++) {
        float2 fA1 = __half22float2(*reinterpret_cast<const __half2*>(&a1[s]));
        float2 fA2 = __half22float2(*reinterpret_cast<const __half2*>(&a2[s]));
        float2 fB1 = __half22float2(*reinterpret_cast<const __half2*>(&b1[s]));
        float2 fB2 = __half22float2(*reinterpret_cast<const __half2*>(&b2[s]));
        acc[s].x = fmaf(wgt[0], fA1.x, fmaf(wgt[1], fA2.x, fmaf(wgt[2], fB1.x, wgt[3] * fB2.x)));
        acc[s].y = fmaf(wgt[0], fA1.y, fmaf(wgt[1], fA2.y, fmaf(wgt[2], fB1.y, wgt[3] * fB2.y)));
    }
    // out_j = sum_i x_i * W[i][j] + B[j]
    o0 = fmaf(x0, acc[0].x, fmaf(x1, acc[1].y, fmaf(x2, acc[3].x, acc[4].y)));
    o1 = fmaf(x0, acc[0].y, fmaf(x1, acc[2].x, fmaf(x2, acc[3].y, acc[5].x)));
    o2 = fmaf(x0, acc[1].x, fmaf(x1, acc[2].y, fmaf(x2, acc[4].x, acc[5].y)));
}

// Two points per thread, processed sequentially to cap register pressure.
__global__ __launch_bounds__(256, 5) void interp_kernel(
    const float* __restrict__ x,
    const int*   __restrict__ m,
    const float* __restrict__ u,
    const float* __restrict__ v,
    float* __restrict__ out,
    int N)
{
    int t2 = blockIdx.x * blockDim.x + threadIdx.x;
    int p0 = t2 * 2;
    if (p0 >= N) return;
    bool dual = (p0 + 1 < N);

    float u0, u1, v0, v1;
    int m0, m1;
    float xv[6];
    if (dual) {
        float2 uf = reinterpret_cast<const float2*>(u)[t2];
        float2 vf = reinterpret_cast<const float2*>(v)[t2];
        int2   mi = reinterpret_cast<const int2*>(m)[t2];
        float2 xa = reinterpret_cast<const float2*>(x)[3 * t2 + 0];
        float2 xb = reinterpret_cast<const float2*>(x)[3 * t2 + 1];
        float2 xc = reinterpret_cast<const float2*>(x)[3 * t2 + 2];
        u0 = uf.x; u1 = uf.y; v0 = vf.x; v1 = vf.y; m0 = mi.x; m1 = mi.y;
        xv[0] = xa.x; xv[1] = xa.y; xv[2] = xb.x;
        xv[3] = xb.y; xv[4] = xc.x; xv[5] = xc.y;
    } else {
        u0 = u[p0]; v0 = v[p0]; m0 = m[p0];
        xv[0] = x[3 * p0]; xv[1] = x[3 * p0 + 1]; xv[2] = x[3 * p0 + 2];
        u1 = 0.f; v1 = 0.f; m1 = 0;
        xv[3] = xv[4] = xv[5] = 0.f;
    }

    const char* base = reinterpret_cast<const char*>(g_tbl);

    unsigned offA0, offB0, offA1, offB1;
    float wgt0[4], wgt1[4];
    point_setup(u0, v0, m0, offA0, offB0, wgt0);
    point_setup(u1, v1, m1, offA1, offB1, wgt1);

    float o00, o01, o02;
    point_process(base, offA0, offB0, wgt0, xv[0], xv[1], xv[2], o00, o01, o02);

    if (dual) {
        float o10, o11, o12;
        point_process(base, offA1, offB1, wgt1, xv[3], xv[4], xv[5], o10, o11, o12);
        float2* o2p = reinterpret_cast<float2*>(out) + 3 * t2;
        o2p[0] = make_float2(o00, o01);
        o2p[1] = make_float2(o02, o10);
        o2p[2] = make_float2(o11, o12);
    } else {
        out[3 * p0 + 0] = o00;
        out[3 * p0 + 1] = o01;
        out[3 * p0 + 2] = o02;
    }
}

extern "C" void kernel_launch(void* const* d_in, const int* in_sizes, int n_in,
                              void* d_out, int out_size) {
    const float* x       = (const float*)d_in[0];   // [N,3]
    const int*   m       = (const int*)  d_in[1];   // [N]
    const float* u       = (const float*)d_in[2];   // [N]
    const float* v       = (const float*)d_in[3];   // [N]
    const float* m_param = (const float*)d_in[4];   // [M,U*V,3,3]
    const float* b_param = (const float*)d_in[5];   // [M,U*V,1,3]
    float* out = (float*)d_out;

    int N = in_sizes[1];  // element count of m

    // Stage 1: streaming convert to compact fp16 records (20.5 MB, L2-resident)
    {
        int blocks = (NTEXP + 255) / 256;
        pack_kernel<<<blocks, 256>>>(m_param, b_param);
    }
    // Stage 2: gather (4x LDG.256 per point, 2 points sequential per thread)
    {
        int npair = (N + 1) / 2;
        int blocks = (npair + 255) / 256;
        interp_kernel<<<blocks, 256>>>(x, m, u, v, out, N);
    }
}

// round 11
// speedup vs baseline: 1.0291x; 1.0291x over previous
#include <cuda_runtime.h>
#include <cuda_fp16.h>

// Problem dims (fixed by reference)
#define UDIM 400
#define VDIM 400
#define MDIM 4
#define VPAD (VDIM + 1)                    // duplicate column 0 at j=400 -> no j-wrap
#define NTEXP (MDIM * UDIM * VPAD)         // 641,600 padded texels

// Compact fp16 table: per texel one 32B record (16 halves):
// [W00..W22 row-major (9), B0,B1,B2 (3), pad (4)].
// j-contiguous with VPAD -> a (j, j+1) pair is 64B contiguous, 32B-aligned.
// Total 20.5 MB -> L2-resident.
__device__ __align__(32) unsigned g_tbl[(size_t)NTEXP * 8];

__global__ __launch_bounds__(256) void pack_kernel(
    const float* __restrict__ m_param,
    const float* __restrict__ b_param)
{
    int t = blockIdx.x * blockDim.x + threadIdx.x;
    if (t >= NTEXP) return;
    int m  = t / (UDIM * VPAD);
    int r  = t % (UDIM * VPAD);
    int i  = r / VPAD;
    int jp = r % VPAD;
    int j  = (jp == VDIM) ? 0 : jp;         // padded column duplicates j=0
    size_t src = (size_t)(m * UDIM + i) * VDIM + j;

    const float* w = m_param + src * 9;
    const float* b = b_param + src * 3;

    __align__(32) __half h[16];
    #pragma unroll
    for (int k = 0; k < 9; k++) h[k] = __float2half_rn(w[k]);
    #pragma unroll
    for (int k = 0; k < 3; k++) h[9 + k] = __float2half_rn(b[k]);
    h[12] = h[13] = h[14] = h[15] = __half(0.0f);

    const uint4* s = reinterpret_cast<const uint4*>(h);
    uint4* dst = reinterpret_cast<uint4*>(g_tbl + (size_t)t * 8);
    dst[0] = s[0];
    dst[1] = s[1];
}

__device__ __forceinline__ void ldg256(const void* p, unsigned r[8]) {
    asm("ld.global.nc.v8.b32 {%0,%1,%2,%3,%4,%5,%6,%7}, [%8];"
        : "=r"(r[0]), "=r"(r[1]), "=r"(r[2]), "=r"(r[3]),
          "=r"(r[4]), "=r"(r[5]), "=r"(r[6]), "=r"(r[7])
        : "l"(p));
}

// Compute rowA/rowB byte offsets (u32) + (ir, jr) fractions for one point.
__device__ __forceinline__ void point_setup(float uu, float vv, int mm,
                                            unsigned& offA, unsigned& offB,
                                            float& ir, float& jr) {
    float iu = uu * (float)UDIM;
    float iv = vv * (float)VDIM;
    if (iu == (float)UDIM) iu = (float)(UDIM - 1);
    if (iv == (float)VDIM) iv = (float)(VDIM - 1);

    float i1f = floorf(iu);
    float j1f = floorf(iv);
    int i1 = (int)i1f;
    int j1 = (int)j1f;                       // j2 via padded column
    int i2 = i1 + 1; if (i2 == UDIM) i2 = 0; // i wraps
    ir = iu - i1f;
    jr = iv - j1f;

    offA = (unsigned)((mm * UDIM + i1) * VPAD + j1) * 32u;
    offB = (unsigned)((mm * UDIM + i2) * VPAD + j1) * 32u;
}

// j-blend one corner pair in half2: f = p1*(1-jr) + p2*jr (2 fp16 roundings).
__device__ __forceinline__ void jblend(const unsigned p1[8], const unsigned p2[8],
                                       __half2 jrh, __half2 ijrh, __half2 f[6]) {
    #pragma unroll
    for (int s = 0; s < 6; s++) {
        __half2 h1 = *reinterpret_cast<const __half2*>(&p1[s]);
        __half2 h2 = *reinterpret_cast<const __half2*>(&p2[s]);
        f[s] = __hfma2(h2, jrh, __hmul2(h1, ijrh));
    }
}

// i-blend (fp32) + matvec -> 3 outputs.
__device__ __forceinline__ void point_finish(const __half2 fA[6], const __half2 fB[6],
                                             float ir,
                                             float x0, float x1, float x2,
                                             float& o0, float& o1, float& o2) {
    // slots s=0..5: [0]=(W00,W01) [1]=(W02,W10) [2]=(W11,W12)
    //               [3]=(W20,W21) [4]=(W22,B0)  [5]=(B1,B2)
    float2 acc[6];
    #pragma unroll
    for (int s = 0; s < 6; s++) {
        float2 fa = __half22float2(fA[s]);
        float2 fb = __half22float2(fB[s]);
        acc[s].x = fmaf(ir, fb.x - fa.x, fa.x);
        acc[s].y = fmaf(ir, fb.y - fa.y, fa.y);
    }
    // out_j = sum_i x_i * W[i][j] + B[j]
    o0 = fmaf(x0, acc[0].x, fmaf(x1, acc[1].y, fmaf(x2, acc[3].x, acc[4].y)));
    o1 = fmaf(x0, acc[0].y, fmaf(x1, acc[2].x, fmaf(x2, acc[3].y, acc[5].x)));
    o2 = fmaf(x0, acc[1].x, fmaf(x1, acc[2].y, fmaf(x2, acc[4].x, acc[5].y)));
}

// Two points per thread, all table loads issued up front (max MLP), fp16 j-blend
// retires load registers early -> fits 48-reg cap for 5 blocks/SM.
__global__ __launch_bounds__(256, 5) void interp_kernel(
    const float* __restrict__ x,
    const int*   __restrict__ m,
    const float* __restrict__ u,
    const float* __restrict__ v,
    float* __restrict__ out,
    int N)
{
    int t2 = blockIdx.x * blockDim.x + threadIdx.x;
    int p0 = t2 * 2;
    if (p0 >= N) return;
    bool dual = (p0 + 1 < N);

    float u0, u1, v0, v1;
    int m0, m1;
    float xv[6];
    if (dual) {
        float2 uf = reinterpret_cast<const float2*>(u)[t2];
        float2 vf = reinterpret_cast<const float2*>(v)[t2];
        int2   mi = reinterpret_cast<const int2*>(m)[t2];
        float2 xa = reinterpret_cast<const float2*>(x)[3 * t2 + 0];
        float2 xb = reinterpret_cast<const float2*>(x)[3 * t2 + 1];
        float2 xc = reinterpret_cast<const float2*>(x)[3 * t2 + 2];
        u0 = uf.x; u1 = uf.y; v0 = vf.x; v1 = vf.y; m0 = mi.x; m1 = mi.y;
        xv[0] = xa.x; xv[1] = xa.y; xv[2] = xb.x;
        xv[3] = xb.y; xv[4] = xc.x; xv[5] = xc.y;
    } else {
        u0 = u[p0]; v0 = v[p0]; m0 = m[p0];
        xv[0] = x[3 * p0]; xv[1] = x[3 * p0 + 1]; xv[2] = x[3 * p0 + 2];
        u1 = 0.f; v1 = 0.f; m1 = 0;
        xv[3] = xv[4] = xv[5] = 0.f;
    }

    unsigned offA0, offB0, offA1, offB1;
    float ir0, jr0, ir1, jr1;
    point_setup(u0, v0, m0, offA0, offB0, ir0, jr0);
    point_setup(u1, v1, m1, offA1, offB1, ir1, jr1);

    const char* base = reinterpret_cast<const char*>(g_tbl);

    // Issue all table loads up front for max MLP
    unsigned a1_0[8], a2_0[8], b1_0[8], b2_0[8];
    unsigned a1_1[8], a2_1[8], b1_1[8], b2_1[8];
    ldg256(base + offA0,       a1_0);
    ldg256(base + offA0 + 32u, a2_0);
    ldg256(base + offB0,       b1_0);
    ldg256(base + offB0 + 32u, b2_0);
    if (dual) {
        ldg256(base + offA1,       a1_1);
        ldg256(base + offA1 + 32u, a2_1);
        ldg256(base + offB1,       b1_1);
        ldg256(base + offB1 + 32u, b2_1);
    }

    // Point 0: fp16 j-blend (frees 64 load regs fast), fp32 i-blend + matvec
    __half2 jrh0  = __float2half2_rn(jr0);
    __half2 ijrh0 = __float2half2_rn(1.0f - jr0);
    __half2 fA0[6], fB0[6];
    jblend(a1_0, a2_0, jrh0, ijrh0, fA0);
    jblend(b1_0, b2_0, jrh0, ijrh0, fB0);
    float o00, o01, o02;
    point_finish(fA0, fB0, ir0, xv[0], xv[1], xv[2], o00, o01, o02);

    if (dual) {
        __half2 jrh1  = __float2half2_rn(jr1);
        __half2 ijrh1 = __float2half2_rn(1.0f - jr1);
        __half2 fA1[6], fB1[6];
        jblend(a1_1, a2_1, jrh1, ijrh1, fA1);
        jblend(b1_1, b2_1, jrh1, ijrh1, fB1);
        float o10, o11, o12;
        point_finish(fA1, fB1, ir1, xv[3], xv[4], xv[5], o10, o11, o12);

        float2* o2p = reinterpret_cast<float2*>(out) + 3 * t2;
        o2p[0] = make_float2(o00, o01);
        o2p[1] = make_float2(o02, o10);
        o2p[2] = make_float2(o11, o12);
    } else {
        out[3 * p0 + 0] = o00;
        out[3 * p0 + 1] = o01;
        out[3 * p0 + 2] = o02;
    }
}

extern "C" void kernel_launch(void* const* d_in, const int* in_sizes, int n_in,
                              void* d_out, int out_size) {
    const float* x       = (const float*)d_in[0];   // [N,3]
    const int*   m       = (const int*)  d_in[1];   // [N]
    const float* u       = (const float*)d_in[2];   // [N]
    const float* v       = (const float*)d_in[3];   // [N]
    const float* m_param = (const float*)d_in[4];   // [M,U*V,3,3]
    const float* b_param = (const float*)d_in[5];   // [M,U*V,1,3]
    float* out = (float*)d_out;

    int N = in_sizes[1];  // element count of m

    // Stage 1: streaming convert to compact fp16 records (20.5 MB, L2-resident)
    {
        int blocks = (NTEXP + 255) / 256;
        pack_kernel<<<blocks, 256>>>(m_param, b_param);
    }
    // Stage 2: gather (4x LDG.256 per point, 2 points per thread, fp16 j-blend)
    {
        int npair = (N + 1) / 2;
        int blocks = (npair + 255) / 256;
        interp_kernel<<<blocks, 256>>>(x, m, u, v, out, N);
    }
}

// round 12
// speedup vs baseline: 1.1709x; 1.1379x over previous
#include <cuda_runtime.h>
#include <cuda_fp16.h>

// Problem dims (fixed by reference)
#define UDIM 400
#define VDIM 400
#define MDIM 4
#define VPAD (VDIM + 1)                    // duplicate column 0 at j=400 -> no j-wrap
#define NTEXP (MDIM * UDIM * VPAD)         // 641,600 padded texels

// Compact fp16 table: per texel one 32B record (16 halves):
// [W00..W22 row-major (9), B0,B1,B2 (3), pad (4)].
// j-contiguous with VPAD -> a (j, j+1) pair is 64B contiguous, 32B-aligned.
// Total 20.5 MB -> L2-resident.
__device__ __align__(32) unsigned g_tbl[(size_t)NTEXP * 8];

__global__ __launch_bounds__(256) void pack_kernel(
    const float* __restrict__ m_param,
    const float* __restrict__ b_param)
{
    int t = blockIdx.x * blockDim.x + threadIdx.x;
    if (t >= NTEXP) return;
    int m  = t / (UDIM * VPAD);
    int r  = t % (UDIM * VPAD);
    int i  = r / VPAD;
    int jp = r % VPAD;
    int j  = (jp == VDIM) ? 0 : jp;         // padded column duplicates j=0
    size_t src = (size_t)(m * UDIM + i) * VDIM + j;

    const float* w = m_param + src * 9;
    const float* b = b_param + src * 3;

    __align__(32) __half h[16];
    #pragma unroll
    for (int k = 0; k < 9; k++) h[k] = __float2half_rn(w[k]);
    #pragma unroll
    for (int k = 0; k < 3; k++) h[9 + k] = __float2half_rn(b[k]);
    h[12] = h[13] = h[14] = h[15] = __half(0.0f);

    const uint4* s = reinterpret_cast<const uint4*>(h);
    uint4* dst = reinterpret_cast<uint4*>(g_tbl + (size_t)t * 8);
    dst[0] = s[0];
    dst[1] = s[1];
}

__device__ __forceinline__ void ldg256(const void* p, unsigned r[8]) {
    asm("ld.global.nc.v8.b32 {%0,%1,%2,%3,%4,%5,%6,%7}, [%8];"
        : "=r"(r[0]), "=r"(r[1]), "=r"(r[2]), "=r"(r[3]),
          "=r"(r[4]), "=r"(r[5]), "=r"(r[6]), "=r"(r[7])
        : "l"(p));
}

// Compute rowA/rowB byte offsets (u32) + (ir, jr) fractions for one point.
__device__ __forceinline__ void point_setup(float uu, float vv, int mm,
                                            unsigned& offA, unsigned& offB,
                                            float& ir, float& jr) {
    float iu = uu * (float)UDIM;
    float iv = vv * (float)VDIM;
    if (iu == (float)UDIM) iu = (float)(UDIM - 1);
    if (iv == (float)VDIM) iv = (float)(VDIM - 1);

    float i1f = floorf(iu);
    float j1f = floorf(iv);
    int i1 = (int)i1f;
    int j1 = (int)j1f;                       // j2 via padded column
    int i2 = i1 + 1; if (i2 == UDIM) i2 = 0; // i wraps
    ir = iu - i1f;
    jr = iv - j1f;

    offA = (unsigned)((mm * UDIM + i1) * VPAD + j1) * 32u;
    offB = (unsigned)((mm * UDIM + i2) * VPAD + j1) * 32u;
}

// j-blend one corner pair in half2: f = p1*(1-jr) + p2*jr (fp16 arithmetic).
__device__ __forceinline__ void jblend(const unsigned p1[8], const unsigned p2[8],
                                       __half2 jrh, __half2 ijrh, __half2 f[6]) {
    #pragma unroll
    for (int s = 0; s < 6; s++) {
        __half2 h1 = *reinterpret_cast<const __half2*>(&p1[s]);
        __half2 h2 = *reinterpret_cast<const __half2*>(&p2[s]);
        f[s] = __hfma2(h2, jrh, __hmul2(h1, ijrh));
    }
}

// i-blend (fp32) + matvec -> 3 outputs.
__device__ __forceinline__ void point_finish(const __half2 fA[6], const __half2 fB[6],
                                             float ir,
                                             float x0, float x1, float x2,
                                             float& o0, float& o1, float& o2) {
    // slots s=0..5: [0]=(W00,W01) [1]=(W02,W10) [2]=(W11,W12)
    //               [3]=(W20,W21) [4]=(W22,B0)  [5]=(B1,B2)
    float2 acc[6];
    #pragma unroll
    for (int s = 0; s < 6; s++) {
        float2 fa = __half22float2(fA[s]);
        float2 fb = __half22float2(fB[s]);
        acc[s].x = fmaf(ir, fb.x - fa.x, fa.x);
        acc[s].y = fmaf(ir, fb.y - fa.y, fa.y);
    }
    // out_j = sum_i x_i * W[i][j] + B[j]
    o0 = fmaf(x0, acc[0].x, fmaf(x1, acc[1].y, fmaf(x2, acc[3].x, acc[4].y)));
    o1 = fmaf(x0, acc[0].y, fmaf(x1, acc[2].x, fmaf(x2, acc[3].y, acc[5].x)));
    o2 = fmaf(x0, acc[1].x, fmaf(x1, acc[2].y, fmaf(x2, acc[4].x, acc[5].y)));
}

// Two points per thread, all table loads issued up front (max MLP), fp16 j-blend
// retires load registers early. No occupancy cap: natural regs, no spills.
__global__ __launch_bounds__(256) void interp_kernel(
    const float* __restrict__ x,
    const int*   __restrict__ m,
    const float* __restrict__ u,
    const float* __restrict__ v,
    float* __restrict__ out,
    int N)
{
    int t2 = blockIdx.x * blockDim.x + threadIdx.x;
    int p0 = t2 * 2;
    if (p0 >= N) return;
    bool dual = (p0 + 1 < N);

    float u0, u1, v0, v1;
    int m0, m1;
    float xv[6];
    if (dual) {
        float2 uf = reinterpret_cast<const float2*>(u)[t2];
        float2 vf = reinterpret_cast<const float2*>(v)[t2];
        int2   mi = reinterpret_cast<const int2*>(m)[t2];
        float2 xa = reinterpret_cast<const float2*>(x)[3 * t2 + 0];
        float2 xb = reinterpret_cast<const float2*>(x)[3 * t2 + 1];
        float2 xc = reinterpret_cast<const float2*>(x)[3 * t2 + 2];
        u0 = uf.x; u1 = uf.y; v0 = vf.x; v1 = vf.y; m0 = mi.x; m1 = mi.y;
        xv[0] = xa.x; xv[1] = xa.y; xv[2] = xb.x;
        xv[3] = xb.y; xv[4] = xc.x; xv[5] = xc.y;
    } else {
        u0 = u[p0]; v0 = v[p0]; m0 = m[p0];
        xv[0] = x[3 * p0]; xv[1] = x[3 * p0 + 1]; xv[2] = x[3 * p0 + 2];
        u1 = 0.f; v1 = 0.f; m1 = 0;
        xv[3] = xv[4] = xv[5] = 0.f;
    }

    unsigned offA0, offB0, offA1, offB1;
    float ir0, jr0, ir1, jr1;
    point_setup(u0, v0, m0, offA0, offB0, ir0, jr0);
    point_setup(u1, v1, m1, offA1, offB1, ir1, jr1);

    const char* base = reinterpret_cast<const char*>(g_tbl);

    // Issue all table loads up front for max MLP
    unsigned a1_0[8], a2_0[8], b1_0[8], b2_0[8];
    unsigned a1_1[8], a2_1[8], b1_1[8], b2_1[8];
    ldg256(base + offA0,       a1_0);
    ldg256(base + offA0 + 32u, a2_0);
    ldg256(base + offB0,       b1_0);
    ldg256(base + offB0 + 32u, b2_0);
    if (dual) {
        ldg256(base + offA1,       a1_1);
        ldg256(base + offA1 + 32u, a2_1);
        ldg256(base + offB1,       b1_1);
        ldg256(base + offB1 + 32u, b2_1);
    }

    // Point 0: fp16 j-blend (frees load regs fast), fp32 i-blend + matvec
    __half2 jrh0  = __float2half2_rn(jr0);
    __half2 ijrh0 = __float2half2_rn(1.0f - jr0);
    __half2 fA0[6], fB0[6];
    jblend(a1_0, a2_0, jrh0, ijrh0, fA0);
    jblend(b1_0, b2_0, jrh0, ijrh0, fB0);
    float o00, o01, o02;
    point_finish(fA0, fB0, ir0, xv[0], xv[1], xv[2], o00, o01, o02);

    if (dual) {
        __half2 jrh1  = __float2half2_rn(jr1);
        __half2 ijrh1 = __float2half2_rn(1.0f - jr1);
        __half2 fA1[6], fB1[6];
        jblend(a1_1, a2_1, jrh1, ijrh1, fA1);
        jblend(b1_1, b2_1, jrh1, ijrh1, fB1);
        float o10, o11, o12;
        point_finish(fA1, fB1, ir1, xv[3], xv[4], xv[5], o10, o11, o12);

        float2* o2p = reinterpret_cast<float2*>(out) + 3 * t2;
        o2p[0] = make_float2(o00, o01);
        o2p[1] = make_float2(o02, o10);
        o2p[2] = make_float2(o11, o12);
    } else {
        out[3 * p0 + 0] = o00;
        out[3 * p0 + 1] = o01;
        out[3 * p0 + 2] = o02;
    }
}

extern "C" void kernel_launch(void* const* d_in, const int* in_sizes, int n_in,
                              void* d_out, int out_size) {
    const float* x       = (const float*)d_in[0];   // [N,3]
    const int*   m       = (const int*)  d_in[1];   // [N]
    const float* u       = (const float*)d_in[2];   // [N]
    const float* v       = (const float*)d_in[3];   // [N]
    const float* m_param = (const float*)d_in[4];   // [M,U*V,3,3]
    const float* b_param = (const float*)d_in[5];   // [M,U*V,1,3]
    float* out = (float*)d_out;

    int N = in_sizes[1];  // element count of m

    // Stage 1: streaming convert to compact fp16 records (20.5 MB, L2-resident)
    {
        int blocks = (NTEXP + 255) / 256;
        pack_kernel<<<blocks, 256>>>(m_param, b_param);
    }
    // Stage 2: gather (4x LDG.256 per point, 2 points per thread, fp16 j-blend)
    {
        int npair = (N + 1) / 2;
        int blocks = (npair + 255) / 256;
        interp_kernel<<<blocks, 256>>>(x, m, u, v, out, N);
    }
}

// round 13
// speedup vs baseline: 1.3582x; 1.1599x over previous
#include <cuda_runtime.h>
#include <cuda_fp16.h>

// Problem dims (fixed by reference)
#define UDIM 400
#define VDIM 400
#define MDIM 4
#define VPAD (VDIM + 1)                    // duplicate column 0 at j=400 -> no j-wrap
#define NTEXP (MDIM * UDIM * VPAD)         // 641,600 padded texels

// Compact fp16 table: per texel one 32B record (16 halves):
// [W00..W22 row-major (9), B0,B1,B2 (3), pad (4)].
// j-contiguous with VPAD -> a (j, j+1) pair is 64B contiguous, 32B-aligned.
// Total 20.5 MB -> L2-resident.
__device__ __align__(32) unsigned g_tbl[(size_t)NTEXP * 8];

__global__ __launch_bounds__(256) void pack_kernel(
    const float* __restrict__ m_param,
    const float* __restrict__ b_param)
{
    int t = blockIdx.x * blockDim.x + threadIdx.x;
    if (t >= NTEXP) return;
    int m  = t / (UDIM * VPAD);
    int r  = t % (UDIM * VPAD);
    int i  = r / VPAD;
    int jp = r % VPAD;
    int j  = (jp == VDIM) ? 0 : jp;         // padded column duplicates j=0
    size_t src = (size_t)(m * UDIM + i) * VDIM + j;

    const float* w = m_param + src * 9;
    const float* b = b_param + src * 3;

    __align__(32) __half h[16];
    #pragma unroll
    for (int k = 0; k < 9; k++) h[k] = __float2half_rn(w[k]);
    #pragma unroll
    for (int k = 0; k < 3; k++) h[9 + k] = __float2half_rn(b[k]);
    h[12] = h[13] = h[14] = h[15] = __half(0.0f);

    const uint4* s = reinterpret_cast<const uint4*>(h);
    uint4* dst = reinterpret_cast<uint4*>(g_tbl + (size_t)t * 8);
    dst[0] = s[0];
    dst[1] = s[1];
}

__device__ __forceinline__ void ldg256(const void* p, unsigned r[8]) {
    asm("ld.global.nc.v8.b32 {%0,%1,%2,%3,%4,%5,%6,%7}, [%8];"
        : "=r"(r[0]), "=r"(r[1]), "=r"(r[2]), "=r"(r[3]),
          "=r"(r[4]), "=r"(r[5]), "=r"(r[6]), "=r"(r[7])
        : "l"(p));
}

// Lane-pair cooperative interp: 2 lanes per point.
//   lane even loads corners (i1,j1) and (i2,j1)  [j-weight 1-jr]
//   lane odd  loads corners (i1,j1+1),(i2,j1+1)  [j-weight jr]
// Each lane: i-blend (fp32) -> partial matvec -> scale by j-weight;
// shfl_xor(1) + add completes the point. Even lane stores.
__global__ __launch_bounds__(256) void interp_kernel(
    const float* __restrict__ x,
    const int*   __restrict__ m,
    const float* __restrict__ u,
    const float* __restrict__ v,
    float* __restrict__ out,
    int N)
{
    int tid  = blockIdx.x * blockDim.x + threadIdx.x;
    int gw   = tid >> 5;                 // global warp index
    int lane = tid & 31;
    int pair = lane >> 1;                // 0..15: point slot within warp
    int odd  = lane & 1;

    long long P = (long long)gw * 16 + pair;
    bool valid = (P < (long long)N);
    int t = valid ? (int)P : (N - 1);    // clamp: all lanes stay active for shfl

    // --- setup (both lanes of a pair compute identically; loads merge) ---
    float iu = u[t] * (float)UDIM;
    float iv = v[t] * (float)VDIM;
    if (iu == (float)UDIM) iu = (float)(UDIM - 1);
    if (iv == (float)VDIM) iv = (float)(VDIM - 1);

    float i1f = floorf(iu);
    float j1f = floorf(iv);
    int i1 = (int)i1f;
    int j1 = (int)j1f;                        // j1+1 via padded column
    int i2 = i1 + 1; if (i2 == UDIM) i2 = 0;  // i wraps
    float ir = iu - i1f;
    float jr = iv - j1f;

    int mm = m[t];
    unsigned offA = (unsigned)((mm * UDIM + i1) * VPAD + j1) * 32u;
    unsigned offB = (unsigned)((mm * UDIM + i2) * VPAD + j1) * 32u;
    unsigned jo = odd ? 32u : 0u;             // odd lane takes the j+1 record

    // --- cooperative gather: 2 LDG.256 per lane; adjacent lanes share lines ---
    const char* base = reinterpret_cast<const char*>(g_tbl);
    unsigned recA[8], recB[8];
    ldg256(base + offA + jo, recA);           // (i1, j1+odd)
    ldg256(base + offB + jo, recB);           // (i2, j1+odd)

    float x0 = x[3 * t + 0];
    float x1 = x[3 * t + 1];
    float x2 = x[3 * t + 2];

    // --- i-blend in fp32; record half2 slots s=0..5:
    // [0]=(W00,W01) [1]=(W02,W10) [2]=(W11,W12) [3]=(W20,W21) [4]=(W22,B0) [5]=(B1,B2)
    float2 acc[6];
    #pragma unroll
    for (int s = 0; s < 6; s++) {
        float2 fa = __half22float2(*reinterpret_cast<const __half2*>(&recA[s]));
        float2 fb = __half22float2(*reinterpret_cast<const __half2*>(&recB[s]));
        acc[s].x = fmaf(ir, fb.x - fa.x, fa.x);
        acc[s].y = fmaf(ir, fb.y - fa.y, fa.y);
    }

    // partial matvec: y_lane = x . W_lane + B_lane, then scale by j-weight
    float jw = odd ? jr : (1.0f - jr);
    float o0 = fmaf(x0, acc[0].x, fmaf(x1, acc[1].y, fmaf(x2, acc[3].x, acc[4].y))) * jw;
    float o1 = fmaf(x0, acc[0].y, fmaf(x1, acc[2].x, fmaf(x2, acc[3].y, acc[5].x))) * jw;
    float o2 = fmaf(x0, acc[1].x, fmaf(x1, acc[2].y, fmaf(x2, acc[4].x, acc[5].y))) * jw;

    // combine the lane pair
    o0 += __shfl_xor_sync(0xffffffffu, o0, 1);
    o1 += __shfl_xor_sync(0xffffffffu, o1, 1);
    o2 += __shfl_xor_sync(0xffffffffu, o2, 1);

    if (valid && !odd) {
        out[3 * t + 0] = o0;
        out[3 * t + 1] = o1;
        out[3 * t + 2] = o2;
    }
}

extern "C" void kernel_launch(void* const* d_in, const int* in_sizes, int n_in,
                              void* d_out, int out_size) {
    const float* x       = (const float*)d_in[0];   // [N,3]
    const int*   m       = (const int*)  d_in[1];   // [N]
    const float* u       = (const float*)d_in[2];   // [N]
    const float* v       = (const float*)d_in[3];   // [N]
    const float* m_param = (const float*)d_in[4];   // [M,U*V,3,3]
    const float* b_param = (const float*)d_in[5];   // [M,U*V,1,3]
    float* out = (float*)d_out;

    int N = in_sizes[1];  // element count of m

    // Stage 1: streaming convert to compact fp16 records (20.5 MB, L2-resident)
    {
        int blocks = (NTEXP + 255) / 256;
        pack_kernel<<<blocks, 256>>>(m_param, b_param);
    }
    // Stage 2: lane-pair cooperative gather + blend + matvec (16 points/warp)
    {
        long long warps = ((long long)N + 15) / 16;
        long long threads_total = warps * 32;
        int blocks = (int)((threads_total + 255) / 256);
        interp_kernel<<<blocks, 256>>>(x, m, u, v, out, N);
    }
}

// round 14
// speedup vs baseline: 1.4382x; 1.0589x over previous
#include <cuda_runtime.h>
#include <cuda_fp16.h>

// Problem dims (fixed by reference)
#define UDIM 400
#define VDIM 400
#define MDIM 4
#define NTEX (MDIM * UDIM * VDIM)          // 640,000 records

// j-pair fp16 table: per texel (m,i,j) one 64B record (32 halves):
//   halves [ 0..11] = texel (i, j):   W00..W22 row-major, B0,B1,B2
//   halves [12..15] = pad
//   halves [16..27] = texel (i, j+1 mod 400)  (j-wrap baked in)
//   halves [28..31] = pad
// 64B-aligned -> a lane pair's two 32B halves ALWAYS share one 128B line.
__device__ __align__(64) unsigned g_tbl[(size_t)NTEX * 16];

// Single-stage pack: thread t -> record (m,i,j). Reads texels (i,j) and (i,j+1)
// from fp32 sources (adjacent threads read overlapping rows -> L2-served),
// writes one coalesced 64B record.
__global__ __launch_bounds__(256) void pack_kernel(
    const float* __restrict__ m_param,
    const float* __restrict__ b_param)
{
    int t = blockIdx.x * blockDim.x + threadIdx.x;
    if (t >= NTEX) return;
    int j  = t % VDIM;
    int j2 = j + 1; if (j2 == VDIM) j2 = 0;
    size_t src1 = (size_t)t;                    // (m,i,j) linear
    size_t src2 = (size_t)(t - j + j2);         // (m,i,j2) linear

    __align__(64) __half h[32];
    {
        const float* w = m_param + src1 * 9;
        const float* b = b_param + src1 * 3;
        #pragma unroll
        for (int k = 0; k < 9; k++) h[k] = __float2half_rn(w[k]);
        #pragma unroll
        for (int k = 0; k < 3; k++) h[9 + k] = __float2half_rn(b[k]);
        h[12] = h[13] = h[14] = h[15] = __half(0.0f);
    }
    {
        const float* w = m_param + src2 * 9;
        const float* b = b_param + src2 * 3;
        #pragma unroll
        for (int k = 0; k < 9; k++) h[16 + k] = __float2half_rn(w[k]);
        #pragma unroll
        for (int k = 0; k < 3; k++) h[25 + k] = __float2half_rn(b[k]);
        h[28] = h[29] = h[30] = h[31] = __half(0.0f);
    }

    const uint4* s = reinterpret_cast<const uint4*>(h);
    uint4* dst = reinterpret_cast<uint4*>(g_tbl + (size_t)t * 16);
    dst[0] = s[0]; dst[1] = s[1]; dst[2] = s[2]; dst[3] = s[3];
}

__device__ __forceinline__ void ldg256(const void* p, unsigned r[8]) {
    asm("ld.global.nc.v8.b32 {%0,%1,%2,%3,%4,%5,%6,%7}, [%8];"
        : "=r"(r[0]), "=r"(r[1]), "=r"(r[2]), "=r"(r[3]),
          "=r"(r[4]), "=r"(r[5]), "=r"(r[6]), "=r"(r[7])
        : "l"(p));
}

// Lane-pair cooperative interp: 2 lanes per point.
//   lane even -> j-half (offset +0),  weight (1-jr)
//   lane odd  -> j+1-half (offset +32), weight jr
// Both halves of a record share one 128B line (64B-aligned) -> guaranteed merge.
__global__ __launch_bounds__(256) void interp_kernel(
    const float* __restrict__ x,
    const int*   __restrict__ m,
    const float* __restrict__ u,
    const float* __restrict__ v,
    float* __restrict__ out,
    int N)
{
    int tid  = blockIdx.x * blockDim.x + threadIdx.x;
    int gw   = tid >> 5;                 // global warp index
    int lane = tid & 31;
    int pair = lane >> 1;                // 0..15: point slot within warp
    int odd  = lane & 1;

    long long P = (long long)gw * 16 + pair;
    bool valid = (P < (long long)N);
    int t = valid ? (int)P : (N - 1);    // clamp: all lanes stay active for shfl

    // --- setup (both lanes of a pair compute identically; loads merge) ---
    float iu = u[t] * (float)UDIM;
    float iv = v[t] * (float)VDIM;
    if (iu == (float)UDIM) iu = (float)(UDIM - 1);
    if (iv == (float)VDIM) iv = (float)(VDIM - 1);

    float i1f = floorf(iu);
    float j1f = floorf(iv);
    int i1 = (int)i1f;
    int j1 = (int)j1f;                        // j+1 half lives inside the record
    int i2 = i1 + 1; if (i2 == UDIM) i2 = 0;  // i wraps
    float ir = iu - i1f;
    float jr = iv - j1f;

    int mm = m[t];
    unsigned offA = (unsigned)((mm * UDIM + i1) * VDIM + j1) * 64u;
    unsigned offB = (unsigned)((mm * UDIM + i2) * VDIM + j1) * 64u;
    unsigned jo = odd ? 32u : 0u;             // odd lane takes the j+1 half

    // --- cooperative gather: 2 LDG.256 per lane; pair always shares the line ---
    const char* base = reinterpret_cast<const char*>(g_tbl);
    unsigned recA[8], recB[8];
    ldg256(base + offA + jo, recA);           // (i1, j1+odd)
    ldg256(base + offB + jo, recB);           // (i2, j1+odd)

    float x0 = x[3 * t + 0];
    float x1 = x[3 * t + 1];
    float x2 = x[3 * t + 2];

    // --- i-blend in fp32; record half2 slots s=0..5:
    // [0]=(W00,W01) [1]=(W02,W10) [2]=(W11,W12) [3]=(W20,W21) [4]=(W22,B0) [5]=(B1,B2)
    float2 acc[6];
    #pragma unroll
    for (int s = 0; s < 6; s++) {
        float2 fa = __half22float2(*reinterpret_cast<const __half2*>(&recA[s]));
        float2 fb = __half22float2(*reinterpret_cast<const __half2*>(&recB[s]));
        acc[s].x = fmaf(ir, fb.x - fa.x, fa.x);
        acc[s].y = fmaf(ir, fb.y - fa.y, fa.y);
    }

    // partial matvec: y_lane = x . W_lane + B_lane, then scale by j-weight
    float jw = odd ? jr : (1.0f - jr);
    float o0 = fmaf(x0, acc[0].x, fmaf(x1, acc[1].y, fmaf(x2, acc[3].x, acc[4].y))) * jw;
    float o1 = fmaf(x0, acc[0].y, fmaf(x1, acc[2].x, fmaf(x2, acc[3].y, acc[5].x))) * jw;
    float o2 = fmaf(x0, acc[1].x, fmaf(x1, acc[2].y, fmaf(x2, acc[4].x, acc[5].y))) * jw;

    // combine the lane pair
    o0 += __shfl_xor_sync(0xffffffffu, o0, 1);
    o1 += __shfl_xor_sync(0xffffffffu, o1, 1);
    o2 += __shfl_xor_sync(0xffffffffu, o2, 1);

    if (valid && !odd) {
        out[3 * t + 0] = o0;
        out[3 * t + 1] = o1;
        out[3 * t + 2] = o2;
    }
}

extern "C" void kernel_launch(void* const* d_in, const int* in_sizes, int n_in,
                              void* d_out, int out_size) {
    const float* x       = (const float*)d_in[0];   // [N,3]
    const int*   m       = (const int*)  d_in[1];   // [N]
    const float* u       = (const float*)d_in[2];   // [N]
    const float* v       = (const float*)d_in[3];   // [N]
    const float* m_param = (const float*)d_in[4];   // [M,U*V,3,3]
    const float* b_param = (const float*)d_in[5];   // [M,U*V,1,3]
    float* out = (float*)d_out;

    int N = in_sizes[1];  // element count of m

    // Stage 1: build 64B j-pair fp16 records (41 MB), single streaming pass
    {
        int blocks = (NTEX + 255) / 256;
        pack_kernel<<<blocks, 256>>>(m_param, b_param);
    }
    // Stage 2: lane-pair cooperative gather + blend + matvec (16 points/warp)
    {
        long long warps = ((long long)N + 15) / 16;
        long long threads_total = warps * 32;
        int blocks = (int)((threads_total + 255) / 256);
        interp_kernel<<<blocks, 256>>>(x, m, u, v, out, N);
    }
}